// round 10
// baseline (speedup 1.0000x reference)
#include <cuda_runtime.h>
#include <float.h>
#include <stdint.h>

#define D2 64
#define MAX_TABLE_LEN 8192
#define PREPB 264
#define ROWS_PER_WARP 4

// Scratch (no allocation allowed in kernel_launch)
__device__ __align__(16) float g_sx2[MAX_TABLE_LEN * D2];  // pairsum(x)
__device__ __align__(16) float g_sy2[MAX_TABLE_LEN * D2];  // pairsum(y)
__device__ __align__(16) float g_f2 [MAX_TABLE_LEN * D2];  // pairsum(fixed)
__device__ float g_pmx[PREPB];
__device__ float g_pmy[PREPB];
__device__ float g_inv2[2];
__device__ unsigned int g_done = 0;  // fence-counter; last block resets to 0

// ---------------------------------------------------------------------------
// K1: single-pass prep. Reads x, y, f once; writes UNSCALED pair-sum tables
//   Sx2[i][j] = x[i][2j]+x[i][2j+1]   (same for Sy2, F2)
// while tracking global max of x and y. The LAST block to finish
// (fence-counter, no spin — proven pattern) reduces partials -> g_inv2.
// 264 blocks x 256 thr, one 2-way-batched pass (264*256*2 >= n4), all 6
// loads front-batched per thread.
// ---------------------------------------------------------------------------
__global__ void __launch_bounds__(256)
prep_kernel(const float4* __restrict__ x, const float4* __restrict__ y,
            const float4* __restrict__ f, int n4) {
    const int tid = threadIdx.x;
    const int stride = PREPB * 256;
    const int i0 = blockIdx.x * 256 + tid;
    const int i1 = i0 + stride;
    const bool ok0 = (i0 < n4);
    const bool ok1 = (i1 < n4);

    float4 xa0, ya0, fa0, xa1, ya1, fa1;
    // Front-batch all loads before any dependent math.
    if (ok0) { xa0 = x[i0]; ya0 = y[i0]; fa0 = f[i0]; }
    if (ok1) { xa1 = x[i1]; ya1 = y[i1]; fa1 = f[i1]; }

    float mx = -FLT_MAX, my = -FLT_MAX;
    if (ok0) {
        ((float2*)g_sx2)[i0] = make_float2(xa0.x + xa0.y, xa0.z + xa0.w);
        ((float2*)g_sy2)[i0] = make_float2(ya0.x + ya0.y, ya0.z + ya0.w);
        ((float2*)g_f2 )[i0] = make_float2(fa0.x + fa0.y, fa0.z + fa0.w);
        mx = fmaxf(mx, fmaxf(fmaxf(xa0.x, xa0.y), fmaxf(xa0.z, xa0.w)));
        my = fmaxf(my, fmaxf(fmaxf(ya0.x, ya0.y), fmaxf(ya0.z, ya0.w)));
    }
    if (ok1) {
        ((float2*)g_sx2)[i1] = make_float2(xa1.x + xa1.y, xa1.z + xa1.w);
        ((float2*)g_sy2)[i1] = make_float2(ya1.x + ya1.y, ya1.z + ya1.w);
        ((float2*)g_f2 )[i1] = make_float2(fa1.x + fa1.y, fa1.z + fa1.w);
        mx = fmaxf(mx, fmaxf(fmaxf(xa1.x, xa1.y), fmaxf(xa1.z, xa1.w)));
        my = fmaxf(my, fmaxf(fmaxf(ya1.x, ya1.y), fmaxf(ya1.z, ya1.w)));
    }

#pragma unroll
    for (int o = 16; o > 0; o >>= 1) {
        mx = fmaxf(mx, __shfl_xor_sync(0xFFFFFFFFu, mx, o));
        my = fmaxf(my, __shfl_xor_sync(0xFFFFFFFFu, my, o));
    }
    __shared__ float smx[8], smy[8];
    __shared__ bool s_last;
    int w = tid >> 5, l = tid & 31;
    if (l == 0) { smx[w] = mx; smy[w] = my; }
    __syncthreads();
    if (tid == 0) {
        for (int i = 1; i < 8; i++) {
            mx = fmaxf(mx, smx[i]);
            my = fmaxf(my, smy[i]);
        }
        g_pmx[blockIdx.x] = mx;
        g_pmy[blockIdx.x] = my;
        __threadfence();
        unsigned int prev = atomicAdd(&g_done, 1u);
        s_last = (prev == PREPB - 1);
    }
    __syncthreads();

    // Last-finishing block reduces the partial maxes (warp 0 only).
    if (s_last && tid < 32) {
        float fx = -FLT_MAX, fy = -FLT_MAX;
        for (int i = tid; i < PREPB; i += 32) {
            fx = fmaxf(fx, g_pmx[i]);
            fy = fmaxf(fy, g_pmy[i]);
        }
#pragma unroll
        for (int o = 16; o > 0; o >>= 1) {
            fx = fmaxf(fx, __shfl_xor_sync(0xFFFFFFFFu, fx, o));
            fy = fmaxf(fy, __shfl_xor_sync(0xFFFFFFFFu, fy, o));
        }
        if (tid == 0) {
            g_inv2[0] = 0.1f / fx;
            g_inv2[1] = 0.1f / fy;
            g_done = 0;  // reset for next graph replay
        }
    }
}

// ---------------------------------------------------------------------------
// K2: gather + on-the-fly scale. 4 rows/warp; per row each lane issues TWO
// independent 16B gathers (S table + F2 table, both L2-resident, 3MB total)
// -> 8 loads in flight per thread. v = s*inv + f2 (one FMA per element).
// lanes 0-15: x half (Sx2, inv_x); lanes 16-31: y half (Sy2, inv_y).
// Streaming stores: output never re-read, keep tables L2-hot.
// ---------------------------------------------------------------------------
__global__ void __launch_bounds__(256)
gather_kernel(const int2* __restrict__ pos, float4* __restrict__ out,
              int nrows) {
    int warp = (blockIdx.x * blockDim.x + threadIdx.x) >> 5;
    int lane = threadIdx.x & 31;
    int base = warp * ROWS_PER_WARP;
    if (base >= nrows) return;

    bool use_x = (lane < 16);
    int off = lane & 15;
    const float4* stab = use_x ? (const float4*)g_sx2 : (const float4*)g_sy2;
    const float4* ftab = (const float4*)g_f2;
    const float inv = use_x ? g_inv2[0] : g_inv2[1];   // L2 broadcast

    int idx[ROWS_PER_WARP];
#pragma unroll
    for (int k = 0; k < ROWS_PER_WARP; k++) {
        int r = base + k;
        int2 p = (r < nrows) ? __ldg(&pos[r]) : make_int2(1, 1);
        int t = use_x ? p.x : p.y;
        idx[k] = (t < 0) ? 1 : t;
    }

    float4 s[ROWS_PER_WARP], f2v[ROWS_PER_WARP];
#pragma unroll
    for (int k = 0; k < ROWS_PER_WARP; k++) {
        size_t o = (size_t)idx[k] * 16 + off;
        s[k]   = __ldg(stab + o);
        f2v[k] = __ldg(ftab + o);
    }

#pragma unroll
    for (int k = 0; k < ROWS_PER_WARP; k++) {
        int r = base + k;
        if (r < nrows) {
            float4 v;
            v.x = fmaf(s[k].x, inv, f2v[k].x);
            v.y = fmaf(s[k].y, inv, f2v[k].y);
            v.z = fmaf(s[k].z, inv, f2v[k].z);
            v.w = fmaf(s[k].w, inv, f2v[k].w);
            __stcs(&out[(size_t)r * 32 + lane], v);
        }
    }
}

extern "C" void kernel_launch(void* const* d_in, const int* in_sizes, int n_in,
                              void* d_out, int out_size) {
    const int*   positions   = (const int*)d_in[0];   // [16,512,32,2] int32
    const float* fixed_table = (const float*)d_in[1]; // [table_len,128]
    const float* table_x     = (const float*)d_in[2];
    const float* table_y     = (const float*)d_in[3];

    int table_elems = in_sizes[1];        // table_len * 128
    int n4_tab      = table_elems / 4;    // float4 count per table
    int nrows       = in_sizes[0] / 2;    // 262144 output rows

    prep_kernel<<<PREPB, 256>>>((const float4*)table_x,
                                (const float4*)table_y,
                                (const float4*)fixed_table, n4_tab);
    {
        int threads = 256;  // 8 warps/block, 4 rows/warp
        int nwarps = (nrows + ROWS_PER_WARP - 1) / ROWS_PER_WARP;
        int blocks = (nwarps * 32 + threads - 1) / threads;
        gather_kernel<<<blocks, threads>>>((const int2*)positions,
                                           (float4*)d_out, nrows);
    }
}

// round 12
// speedup vs baseline: 1.1990x; 1.1990x over previous
#include <cuda_runtime.h>
#include <cuda_fp16.h>
#include <float.h>
#include <stdint.h>

#define D2 64
#define MAX_TABLE_LEN 8192
#define MAXB_MAX 132
#define MAXB_BUILD 264
#define ROWS_PER_WARP 8

// Scratch (no allocation allowed in kernel_launch)
// Combined pair-reduced tables in FP16: halves LTS read traffic in the gather
// (the LTS-throughput bottleneck) and shrinks the working set to ~1MB.
__device__ __align__(16) __half g_thx2[MAX_TABLE_LEN * D2];
__device__ __align__(16) __half g_thy2[MAX_TABLE_LEN * D2];
__device__ float g_pmx[MAXB_MAX];
__device__ float g_pmy[MAXB_MAX];
__device__ float g_inv2[2];
__device__ unsigned int g_done = 0;  // fence-counter; last block resets to 0

// ---------------------------------------------------------------------------
// Pass 1: global max of both tables (identical to the twice-proven R7 kernel).
// 132 blocks x 256 thr; 4-way front-batched predicated float4 loads per table.
// LAST block to finish (fence-counter, no spin) reduces partials -> g_inv2.
// ---------------------------------------------------------------------------
__global__ void __launch_bounds__(256)
max_kernel(const float4* __restrict__ x, const float4* __restrict__ y, int n4) {
    const int tid = threadIdx.x;
    const int stride = MAXB_MAX * 256;
    int gtid = blockIdx.x * 256 + tid;

    float mx = -FLT_MAX, my = -FLT_MAX;
    int base = gtid;
    while (base < n4) {
        float4 a[4], b[4];
#pragma unroll
        for (int k = 0; k < 4; k++) {
            int i = base + k * stride;
            bool ok = (i < n4);
            a[k] = ok ? x[i] : make_float4(-FLT_MAX, -FLT_MAX, -FLT_MAX, -FLT_MAX);
            b[k] = ok ? y[i] : make_float4(-FLT_MAX, -FLT_MAX, -FLT_MAX, -FLT_MAX);
        }
#pragma unroll
        for (int k = 0; k < 4; k++) {
            mx = fmaxf(mx, fmaxf(fmaxf(a[k].x, a[k].y), fmaxf(a[k].z, a[k].w)));
            my = fmaxf(my, fmaxf(fmaxf(b[k].x, b[k].y), fmaxf(b[k].z, b[k].w)));
        }
        base += 4 * stride;
    }

#pragma unroll
    for (int o = 16; o > 0; o >>= 1) {
        mx = fmaxf(mx, __shfl_xor_sync(0xFFFFFFFFu, mx, o));
        my = fmaxf(my, __shfl_xor_sync(0xFFFFFFFFu, my, o));
    }
    __shared__ float smx[8], smy[8];
    __shared__ bool s_last;
    int w = tid >> 5, l = tid & 31;
    if (l == 0) { smx[w] = mx; smy[w] = my; }
    __syncthreads();
    if (tid == 0) {
        for (int i = 1; i < 8; i++) {
            mx = fmaxf(mx, smx[i]);
            my = fmaxf(my, smy[i]);
        }
        g_pmx[blockIdx.x] = mx;
        g_pmy[blockIdx.x] = my;
        __threadfence();
        unsigned int prev = atomicAdd(&g_done, 1u);
        s_last = (prev == MAXB_MAX - 1);
    }
    __syncthreads();

    if (s_last && tid < 32) {
        float fx = -FLT_MAX, fy = -FLT_MAX;
        for (int i = tid; i < MAXB_MAX; i += 32) {
            fx = fmaxf(fx, g_pmx[i]);
            fy = fmaxf(fy, g_pmy[i]);
        }
#pragma unroll
        for (int o = 16; o > 0; o >>= 1) {
            fx = fmaxf(fx, __shfl_xor_sync(0xFFFFFFFFu, fx, o));
            fy = fmaxf(fy, __shfl_xor_sync(0xFFFFFFFFu, fy, o));
        }
        if (tid == 0) {
            g_inv2[0] = 0.1f / fx;
            g_inv2[1] = 0.1f / fy;
            g_done = 0;  // reset for next graph replay
        }
    }
}

// ---------------------------------------------------------------------------
// Pass 2: build COMBINED pair-reduced tables in fp16:
//   THX2[i][j] = half((x[i][2j]+x[i][2j+1]) * invx + (F[i][2j]+F[i][2j+1]))
// 264 blocks x 256 thr, one 2-way-batched pass, loads front-batched.
// x/y are L2-hot from pass 1. Per input float4 -> one half2 (4B) per table.
// ---------------------------------------------------------------------------
__global__ void __launch_bounds__(256)
build_kernel(const float4* __restrict__ x, const float4* __restrict__ y,
             const float4* __restrict__ f, int n4) {
    const int stride = MAXB_BUILD * 256;
    const int i0 = blockIdx.x * 256 + threadIdx.x;
    const int i1 = i0 + stride;
    const bool ok0 = (i0 < n4);
    const bool ok1 = (i1 < n4);

    float4 fa0, xa0, ya0, fa1, xa1, ya1;
    if (ok0) { fa0 = f[i0]; xa0 = x[i0]; ya0 = y[i0]; }
    if (ok1) { fa1 = f[i1]; xa1 = x[i1]; ya1 = y[i1]; }

    const float invx = g_inv2[0];
    const float invy = g_inv2[1];

    if (ok0) {
        float fs0 = fa0.x + fa0.y, fs1 = fa0.z + fa0.w;
        float2 tx = make_float2(fmaf(xa0.x + xa0.y, invx, fs0),
                                fmaf(xa0.z + xa0.w, invx, fs1));
        float2 ty = make_float2(fmaf(ya0.x + ya0.y, invy, fs0),
                                fmaf(ya0.z + ya0.w, invy, fs1));
        ((__half2*)g_thx2)[i0] = __float22half2_rn(tx);
        ((__half2*)g_thy2)[i0] = __float22half2_rn(ty);
    }
    if (ok1) {
        float fs0 = fa1.x + fa1.y, fs1 = fa1.z + fa1.w;
        float2 tx = make_float2(fmaf(xa1.x + xa1.y, invx, fs0),
                                fmaf(xa1.z + xa1.w, invx, fs1));
        float2 ty = make_float2(fmaf(ya1.x + ya1.y, invy, fs0),
                                fmaf(ya1.z + ya1.w, invy, fs1));
        ((__half2*)g_thx2)[i1] = __float22half2_rn(tx);
        ((__half2*)g_thy2)[i1] = __float22half2_rn(ty);
    }
}

// ---------------------------------------------------------------------------
// Pass 3: gather. 8 rows/warp, loads front-batched (MLP=8/thread).
// Table row half = 64 fp16 = 128B; lanes 0-15 each load 8B (uint2 = 4 fp16)
// from THX2[i0], lanes 16-31 from THY2[i1]. Convert to float4, stream out
// 16B per lane -> 512B coalesced per row. Table read traffic halved vs fp32.
// ---------------------------------------------------------------------------
__global__ void __launch_bounds__(256)
gather_kernel(const int2* __restrict__ pos, float4* __restrict__ out,
              int nrows) {
    int warp = (blockIdx.x * blockDim.x + threadIdx.x) >> 5;
    int lane = threadIdx.x & 31;
    int base = warp * ROWS_PER_WARP;
    if (base >= nrows) return;

    bool use_x = (lane < 16);
    int off = lane & 15;
    const uint2* tab = use_x ? (const uint2*)g_thx2 : (const uint2*)g_thy2;

    int idx[ROWS_PER_WARP];
#pragma unroll
    for (int k = 0; k < ROWS_PER_WARP; k++) {
        int r = base + k;
        int2 p = (r < nrows) ? __ldg(&pos[r]) : make_int2(1, 1);
        int t = use_x ? p.x : p.y;
        idx[k] = (t < 0) ? 1 : t;
    }

    uint2 h[ROWS_PER_WARP];
#pragma unroll
    for (int k = 0; k < ROWS_PER_WARP; k++) {
        h[k] = __ldg(tab + (size_t)idx[k] * 16 + off);   // 16 x 8B per row
    }

#pragma unroll
    for (int k = 0; k < ROWS_PER_WARP; k++) {
        int r = base + k;
        if (r < nrows) {
            float2 a = __half22float2(*(const __half2*)&h[k].x);
            float2 b = __half22float2(*(const __half2*)&h[k].y);
            float4 v = make_float4(a.x, a.y, b.x, b.y);
            __stcs(&out[(size_t)r * 32 + lane], v);
        }
    }
}

extern "C" void kernel_launch(void* const* d_in, const int* in_sizes, int n_in,
                              void* d_out, int out_size) {
    const int*   positions   = (const int*)d_in[0];   // [16,512,32,2] int32
    const float* fixed_table = (const float*)d_in[1]; // [table_len,128]
    const float* table_x     = (const float*)d_in[2];
    const float* table_y     = (const float*)d_in[3];

    int table_elems = in_sizes[1];        // table_len * 128
    int n4_tab      = table_elems / 4;    // float4 count per table
    int nrows       = in_sizes[0] / 2;    // 262144 output rows

    max_kernel<<<MAXB_MAX, 256>>>((const float4*)table_x,
                                  (const float4*)table_y, n4_tab);
    build_kernel<<<MAXB_BUILD, 256>>>((const float4*)table_x,
                                      (const float4*)table_y,
                                      (const float4*)fixed_table, n4_tab);
    {
        int threads = 256;  // 8 warps/block, 8 rows/warp
        int nwarps = (nrows + ROWS_PER_WARP - 1) / ROWS_PER_WARP;
        int blocks = (nwarps * 32 + threads - 1) / threads;
        gather_kernel<<<blocks, threads>>>((const int2*)positions,
                                           (float4*)d_out, nrows);
    }
}